// round 6
// baseline (speedup 1.0000x reference)
#include <cuda_runtime.h>
#include <cuda_bf16.h>
#include <cstdint>

#define MAXN 100000
#define FDIM 128
#define NGRAPH 64
#define BK 32

// ---------------- scratch (device globals; referenced ONLY from device code) ---
__device__ float          g_dinv[MAXN];                    // deg -> rsqrt(deg)
__device__ __nv_bfloat16  g_xwsb[(size_t)MAXN * FDIM];     // (A@W)*dinv[row], bf16 (gather payload)
__device__ float          g_agg [(size_t)MAXN * FDIM];     // fp32 aggregation target
__device__ float          g_sums[NGRAPH * FDIM];           // pooling sums
__device__ float          g_cnts[NGRAPH];                  // pooling counts

// ---------------- helpers -------------------------------------------------------
__device__ __forceinline__ uint32_t f2tf32(float f) {
    uint32_t u; asm("cvt.rna.tf32.f32 %0, %1;" : "=r"(u) : "f"(f)); return u;
}
__device__ __forceinline__ void mma_tf32(float* c, const uint32_t* a, const uint32_t* b) {
    asm volatile("mma.sync.aligned.m16n8k8.row.col.f32.tf32.tf32.f32 "
        "{%0,%1,%2,%3}, {%4,%5,%6,%7}, {%8,%9}, {%0,%1,%2,%3};"
        : "+f"(c[0]), "+f"(c[1]), "+f"(c[2]), "+f"(c[3])
        : "r"(a[0]), "r"(a[1]), "r"(a[2]), "r"(a[3]), "r"(b[0]), "r"(b[1]));
}

// ---------------- degree / dinv ------------------------------------------------
__global__ void k_init_deg(int n) {
    int i = blockIdx.x * blockDim.x + threadIdx.x;
    if (i < n) g_dinv[i] = 1.0f;   // self-loop contributes 1
}

__global__ void k_deg_accum(const int* __restrict__ dst, int e, int n) {
    int i = blockIdx.x * blockDim.x + threadIdx.x;
    if (i >= e) return;
    int d = dst[i];
    if ((unsigned)d < (unsigned)n) atomicAdd(&g_dinv[d], 1.0f);
}

__global__ void k_finalize_dinv(int n) {
    int i = blockIdx.x * blockDim.x + threadIdx.x;
    if (i < n) g_dinv[i] = rsqrtf(g_dinv[i]);  // deg >= 1 always (self-loop)
}

// ---------------- tf32 tensor-core GEMM ----------------------------------------
// out = transform(A)[M,128] @ W[128,128], scaled by dinv[row] in epilogue.
// A_ext != null : A = A_ext (layer 1 input x, no transform)
// A_ext == null : A = relu(g_agg * dinv[row] + bias)   (fused previous-layer act)
// Epilogue writes g_agg (fp32, = self-loop init) AND g_xwsb (bf16 gather payload).
// Block tile 128x128, 256 threads (8 warps as 2x4), warp tile 64x32,
// per-warp 4x4 m16n8k8 atoms, K chunked by BK=32.
__global__ __launch_bounds__(256) void k_gemm_tf32(
    const float* __restrict__ A_ext, const float* __restrict__ W,
    const float* __restrict__ bias, int M)
{
    __shared__ float As[128][BK + 4];   // [m][k], stride 36 (conflict-free frags)
    __shared__ float Bs[BK][132];       // [k][n], stride 132

    const int tid    = threadIdx.x;
    const int wid    = tid >> 5;
    const int lane   = tid & 31;
    const int g8     = lane >> 2;       // 0..7
    const int tg     = lane & 3;        // 0..3
    const int warp_m = wid >> 2;        // 0..1
    const int warp_n = wid & 3;         // 0..3
    const int row0   = blockIdx.x * 128;

    float acc[4][4][4];
#pragma unroll
    for (int i = 0; i < 4; i++)
#pragma unroll
        for (int j = 0; j < 4; j++)
#pragma unroll
            for (int r = 0; r < 4; r++) acc[i][j][r] = 0.0f;

    const int lr   = tid >> 1;            // A-load row within tile (0..127)
    const int lcb  = (tid & 1) * 16;      // A-load col base
    const int bk   = tid >> 3;            // B-load k row (0..31)
    const int bnb  = (tid & 7) * 16;      // B-load col base
    const int gr   = row0 + lr;
    const bool fused = (A_ext == nullptr);
    const float srow = (fused && gr < M) ? g_dinv[gr] : 0.0f;

    for (int k0 = 0; k0 < 128; k0 += BK) {
        // ---- load + convert A chunk (with optional fused relu transform) ----
#pragma unroll
        for (int c4 = 0; c4 < 4; c4++) {
            int c = lcb + c4 * 4;                 // col within chunk
            float4 v = make_float4(0.f, 0.f, 0.f, 0.f);
            if (gr < M) {
                if (!fused) {
                    v = *reinterpret_cast<const float4*>(A_ext + (size_t)gr * 128 + k0 + c);
                } else {
                    float4 a  = *reinterpret_cast<const float4*>(g_agg + (size_t)gr * 128 + k0 + c);
                    float4 bb = *reinterpret_cast<const float4*>(bias + k0 + c);
                    v.x = fmaxf(fmaf(a.x, srow, bb.x), 0.0f);
                    v.y = fmaxf(fmaf(a.y, srow, bb.y), 0.0f);
                    v.z = fmaxf(fmaf(a.z, srow, bb.z), 0.0f);
                    v.w = fmaxf(fmaf(a.w, srow, bb.w), 0.0f);
                }
            }
            As[lr][c + 0] = __uint_as_float(f2tf32(v.x));
            As[lr][c + 1] = __uint_as_float(f2tf32(v.y));
            As[lr][c + 2] = __uint_as_float(f2tf32(v.z));
            As[lr][c + 3] = __uint_as_float(f2tf32(v.w));
        }
        // ---- load + convert B chunk ----
#pragma unroll
        for (int c4 = 0; c4 < 4; c4++) {
            int c = bnb + c4 * 4;
            float4 w = *reinterpret_cast<const float4*>(W + (size_t)(k0 + bk) * 128 + c);
            Bs[bk][c + 0] = __uint_as_float(f2tf32(w.x));
            Bs[bk][c + 1] = __uint_as_float(f2tf32(w.y));
            Bs[bk][c + 2] = __uint_as_float(f2tf32(w.z));
            Bs[bk][c + 3] = __uint_as_float(f2tf32(w.w));
        }
        __syncthreads();

        // ---- 4 k8-steps of mma ----
#pragma unroll
        for (int ks = 0; ks < BK; ks += 8) {
            uint32_t afr[4][4], bfr[4][2];
#pragma unroll
            for (int am = 0; am < 4; am++) {
                int m = warp_m * 64 + am * 16;
                afr[am][0] = __float_as_uint(As[m + g8    ][ks + tg    ]);
                afr[am][1] = __float_as_uint(As[m + g8 + 8][ks + tg    ]);
                afr[am][2] = __float_as_uint(As[m + g8    ][ks + tg + 4]);
                afr[am][3] = __float_as_uint(As[m + g8 + 8][ks + tg + 4]);
            }
#pragma unroll
            for (int an = 0; an < 4; an++) {
                int nn = warp_n * 32 + an * 8;
                bfr[an][0] = __float_as_uint(Bs[ks + tg    ][nn + g8]);
                bfr[an][1] = __float_as_uint(Bs[ks + tg + 4][nn + g8]);
            }
#pragma unroll
            for (int am = 0; am < 4; am++)
#pragma unroll
                for (int an = 0; an < 4; an++)
                    mma_tf32(acc[am][an], afr[am], bfr[an]);
        }
        __syncthreads();
    }

    // ---- epilogue: scale by dinv[row]; write agg fp32 + xwsb bf16 ----
#pragma unroll
    for (int am = 0; am < 4; am++) {
        int r1 = row0 + warp_m * 64 + am * 16 + g8;
        int r2 = r1 + 8;
        float s1 = (r1 < M) ? g_dinv[r1] : 0.0f;
        float s2 = (r2 < M) ? g_dinv[r2] : 0.0f;
#pragma unroll
        for (int an = 0; an < 4; an++) {
            int nn = warp_n * 32 + an * 8 + tg * 2;
            if (r1 < M) {
                float2 v = make_float2(acc[am][an][0] * s1, acc[am][an][1] * s1);
                *reinterpret_cast<float2*>(g_agg + (size_t)r1 * 128 + nn) = v;
                *reinterpret_cast<__nv_bfloat162*>(g_xwsb + (size_t)r1 * 128 + nn) =
                    __floats2bfloat162_rn(v.x, v.y);
            }
            if (r2 < M) {
                float2 v = make_float2(acc[am][an][2] * s2, acc[am][an][3] * s2);
                *reinterpret_cast<float2*>(g_agg + (size_t)r2 * 128 + nn) = v;
                *reinterpret_cast<__nv_bfloat162*>(g_xwsb + (size_t)r2 * 128 + nn) =
                    __floats2bfloat162_rn(v.x, v.y);
            }
        }
    }
}

// ---------------- edge scatter: agg[dst] += xwsb[src] (bf16 gather) ------------
// One warp per edge; lane gathers 4 bf16 (8B), converts, one REDG.128 per lane.
__global__ __launch_bounds__(256) void k_edge_agg(
    const int* __restrict__ src, const int* __restrict__ dst, int e, int n)
{
    int warp = (blockIdx.x * blockDim.x + threadIdx.x) >> 5;
    int lane = threadIdx.x & 31;
    if (warp >= e) return;
    int s = src[warp];
    int d = dst[warp];
    if ((unsigned)s >= (unsigned)n || (unsigned)d >= (unsigned)n) return;
    uint2 q = *reinterpret_cast<const uint2*>(g_xwsb + (size_t)s * 128 + lane * 4);
    float2 lo = __bfloat1622float2(*reinterpret_cast<__nv_bfloat162*>(&q.x));
    float2 hi = __bfloat1622float2(*reinterpret_cast<__nv_bfloat162*>(&q.y));
    float* p = g_agg + (size_t)d * 128 + lane * 4;
    asm volatile("red.global.add.v4.f32 [%0], {%1, %2, %3, %4};"
                 :: "l"(p), "f"(lo.x), "f"(lo.y), "f"(hi.x), "f"(hi.y) : "memory");
}

// ---------------- pooling (fused layer-2 activation) ----------------------------
__global__ void k_pool_zero() {
    int i = blockIdx.x * blockDim.x + threadIdx.x;
    if (i < NGRAPH * FDIM) g_sums[i] = 0.0f;
    if (i < NGRAPH)        g_cnts[i] = 0.0f;
}

__global__ __launch_bounds__(256) void k_pool(
    const int* __restrict__ batch, const float* __restrict__ bias, int n)
{
    int node = (blockIdx.x * blockDim.x + threadIdx.x) >> 5;
    int lane = threadIdx.x & 31;
    if (node >= n) return;
    int g = batch[node];
    if ((unsigned)g >= (unsigned)NGRAPH) return;
    float s  = g_dinv[node];
    float4 v = *reinterpret_cast<const float4*>(g_agg + (size_t)node * 128 + lane * 4);
    float4 bb = *reinterpret_cast<const float4*>(bias + lane * 4);
    float4 r;
    r.x = fmaxf(fmaf(v.x, s, bb.x), 0.0f);
    r.y = fmaxf(fmaf(v.y, s, bb.y), 0.0f);
    r.z = fmaxf(fmaf(v.z, s, bb.z), 0.0f);
    r.w = fmaxf(fmaf(v.w, s, bb.w), 0.0f);
    float* p = g_sums + g * 128 + lane * 4;
    asm volatile("red.global.add.v4.f32 [%0], {%1, %2, %3, %4};"
                 :: "l"(p), "f"(r.x), "f"(r.y), "f"(r.z), "f"(r.w) : "memory");
    if (lane == 0) atomicAdd(&g_cnts[g], 1.0f);
}

// ---------------- final head: out[g,o] = (sums[g]/cnt[g]) @ Wlin + blin --------
__global__ void k_final(const float* __restrict__ Wlin, const float* __restrict__ blin,
                        float* __restrict__ out)
{
    int tid = threadIdx.x;
    if (tid >= NGRAPH * 10) return;
    int g = tid / 10;
    int o = tid % 10;
    float inv = 1.0f / fmaxf(g_cnts[g], 1.0f);
    float acc = 0.0f;
#pragma unroll 4
    for (int c = 0; c < 128; c++)
        acc += g_sums[g * 128 + c] * Wlin[c * 10 + o];
    out[tid] = acc * inv + blin[o];
}

// ---------------- launch --------------------------------------------------------
extern "C" void kernel_launch(void* const* d_in, const int* in_sizes, int n_in,
                              void* d_out, int out_size)
{
    const float* x     = (const float*)d_in[0];
    const int*   ei    = (const int*)d_in[1];    // int32 (JAX x64 disabled)
    const int*   batch = (const int*)d_in[2];    // int32
    const float* W1    = (const float*)d_in[3];
    const float* b1    = (const float*)d_in[4];
    const float* W2    = (const float*)d_in[5];
    const float* b2    = (const float*)d_in[6];
    const float* Wlin  = (const float*)d_in[7];
    const float* blin  = (const float*)d_in[8];
    float*       out   = (float*)d_out;

    const int n = in_sizes[0] / FDIM;     // 100000
    const int e = in_sizes[1] / 2;        // 1600000
    const int* src = ei;
    const int* dst = ei + e;

    const int TB = 256;
    int nb_n    = (n + TB - 1) / TB;
    int nb_e    = (e + TB - 1) / TB;
    int nb_gemm = (n + 127) / 128;
    int nb_w    = ((n * 32) + TB - 1) / TB;               // one warp/node
    int nb_ew   = (int)(((size_t)e * 32 + TB - 1) / TB);  // one warp/edge

    // degrees
    k_init_deg     <<<nb_n, TB>>>(n);
    k_deg_accum    <<<nb_e, TB>>>(dst, e, n);
    k_finalize_dinv<<<nb_n, TB>>>(n);

    // layer 1 (A = external x, no transform)
    k_gemm_tf32<<<nb_gemm, TB>>>(x, W1, nullptr, n);
    k_edge_agg <<<nb_ew, TB>>>(src, dst, e, n);

    // layer 2 (A = relu(agg*dinv + b1) fused in A-load)
    k_gemm_tf32<<<nb_gemm, TB>>>(nullptr, W2, b1, n);
    k_edge_agg <<<nb_ew, TB>>>(src, dst, e, n);

    // pooling (fused relu(agg*dinv + b2)) + head
    k_pool_zero<<<(NGRAPH * FDIM + TB - 1) / TB, TB>>>();
    k_pool     <<<nb_w, TB>>>(batch, b2, n);
    k_final    <<<1, 1024>>>(Wlin, blin, out);
}

// round 10
// speedup vs baseline: 2.3853x; 2.3853x over previous
#include <cuda_runtime.h>
#include <cuda_bf16.h>
#include <cstdint>

#define MAXN 100000
#define MAXE 1600000
#define FDIM 128
#define NGRAPH 64
#define BK 32

// ---------------- scratch (device globals; referenced ONLY from device code) ---
__device__ float          g_dinv[MAXN];                    // rsqrt(deg)
__device__ int            g_deg [MAXN];                    // in-degree (no self)
__device__ int            g_rowptr[MAXN + 1];              // CSR row pointers (by dst)
__device__ int            g_cursor[MAXN];                  // scatter cursors
__device__ int            g_csrc[MAXE];                    // CSR column (src) indices
__device__ int            g_blksum[256];                   // scan partials
__device__ __nv_bfloat16  g_xwsb[(size_t)MAXN * FDIM];     // (A@W)*dinv[row], bf16 payload
__device__ float          g_agg [(size_t)MAXN * FDIM];     // fp32 aggregation result
__device__ float          g_sums[NGRAPH * FDIM];           // pooling sums
__device__ float          g_cnts[NGRAPH];                  // pooling counts

// ---------------- helpers -------------------------------------------------------
__device__ __forceinline__ uint32_t f2tf32(float f) {
    uint32_t u; asm("cvt.rna.tf32.f32 %0, %1;" : "=r"(u) : "f"(f)); return u;
}
__device__ __forceinline__ void mma_tf32(float* c, const uint32_t* a, const uint32_t* b) {
    asm volatile("mma.sync.aligned.m16n8k8.row.col.f32.tf32.tf32.f32 "
        "{%0,%1,%2,%3}, {%4,%5,%6,%7}, {%8,%9}, {%0,%1,%2,%3};"
        : "+f"(c[0]), "+f"(c[1]), "+f"(c[2]), "+f"(c[3])
        : "r"(a[0]), "r"(a[1]), "r"(a[2]), "r"(a[3]), "r"(b[0]), "r"(b[1]));
}

// ---------------- degree / dinv ------------------------------------------------
__global__ void k_deg_zero(int n) {
    int i = blockIdx.x * blockDim.x + threadIdx.x;
    if (i < n) g_deg[i] = 0;
}
__global__ void k_deg_count(const int* __restrict__ dst, int e, int n) {
    int i = blockIdx.x * blockDim.x + threadIdx.x;
    if (i >= e) return;
    int d = dst[i];
    if ((unsigned)d < (unsigned)n) atomicAdd(&g_deg[d], 1);
}
__global__ void k_dinv(int n) {
    int i = blockIdx.x * blockDim.x + threadIdx.x;
    if (i < n) g_dinv[i] = rsqrtf((float)(g_deg[i] + 1));   // +1 self-loop
}

// ---------------- exclusive scan of g_deg -> g_rowptr (3 kernels) ---------------
// scan1: 1024 items/block (256 thr x 4), intra-block exclusive scan + block sums
__global__ __launch_bounds__(256) void k_scan1(int n) {
    __shared__ int sh[256];
    int t = threadIdx.x;
    int base = blockIdx.x * 1024 + t * 4;
    int v[4];
#pragma unroll
    for (int i = 0; i < 4; i++) v[i] = (base + i < n) ? g_deg[base + i] : 0;
    int s = v[0] + v[1] + v[2] + v[3];
    sh[t] = s; __syncthreads();
    for (int off = 1; off < 256; off <<= 1) {
        int x = (t >= off) ? sh[t - off] : 0;
        __syncthreads();
        sh[t] += x;
        __syncthreads();
    }
    if (t == 255) g_blksum[blockIdx.x] = sh[255];
    int run = sh[t] - s;
#pragma unroll
    for (int i = 0; i < 4; i++) {
        if (base + i < n) g_rowptr[base + i] = run;
        run += v[i];
    }
}
// scan2: exclusive scan of <=256 block sums, single block
__global__ __launch_bounds__(256) void k_scan2(int nblk) {
    __shared__ int sh[256];
    int t = threadIdx.x;
    int v = (t < nblk) ? g_blksum[t] : 0;
    sh[t] = v; __syncthreads();
    for (int off = 1; off < 256; off <<= 1) {
        int x = (t >= off) ? sh[t - off] : 0;
        __syncthreads();
        sh[t] += x;
        __syncthreads();
    }
    g_blksum[t] = sh[t] - v;
}
// scan3: add block offsets, init cursors, close rowptr
__global__ void k_scan3(int n, int e) {
    int i = blockIdx.x * blockDim.x + threadIdx.x;
    if (i < n) {
        int r = g_rowptr[i] + g_blksum[i >> 10];
        g_rowptr[i] = r;
        g_cursor[i] = r;
    }
    if (i == 0) g_rowptr[n] = e;
}

// ---------------- scatter edges into CSR ---------------------------------------
__global__ void k_scatter(const int* __restrict__ src, const int* __restrict__ dst,
                          int e, int n) {
    int i = blockIdx.x * blockDim.x + threadIdx.x;
    if (i >= e) return;
    int s = src[i], d = dst[i];
    if ((unsigned)s >= (unsigned)n || (unsigned)d >= (unsigned)n) return;
    int pos = atomicAdd(&g_cursor[d], 1);
    if ((unsigned)pos < (unsigned)e) g_csrc[pos] = s;
}

// ---------------- tf32 tensor-core GEMM ----------------------------------------
// xwsb = bf16( transform(A)[M,128] @ W[128,128] * dinv[row] )
// A_ext != null : A = A_ext                  (layer 1 input x)
// A_ext == null : A = relu(g_agg*dinv + bias) (fused previous-layer activation)
__global__ __launch_bounds__(256) void k_gemm_tf32(
    const float* __restrict__ A_ext, const float* __restrict__ W,
    const float* __restrict__ bias, int M)
{
    __shared__ float As[128][BK + 4];
    __shared__ float Bs[BK][132];

    const int tid    = threadIdx.x;
    const int wid    = tid >> 5;
    const int lane   = tid & 31;
    const int g8     = lane >> 2;
    const int tg     = lane & 3;
    const int warp_m = wid >> 2;
    const int warp_n = wid & 3;
    const int row0   = blockIdx.x * 128;

    float acc[4][4][4];
#pragma unroll
    for (int i = 0; i < 4; i++)
#pragma unroll
        for (int j = 0; j < 4; j++)
#pragma unroll
            for (int r = 0; r < 4; r++) acc[i][j][r] = 0.0f;

    const int lr   = tid >> 1;
    const int lcb  = (tid & 1) * 16;
    const int bk   = tid >> 3;
    const int bnb  = (tid & 7) * 16;
    const int gr   = row0 + lr;
    const bool fused = (A_ext == nullptr);
    const float srow = (fused && gr < M) ? g_dinv[gr] : 0.0f;

    for (int k0 = 0; k0 < 128; k0 += BK) {
#pragma unroll
        for (int c4 = 0; c4 < 4; c4++) {
            int c = lcb + c4 * 4;
            float4 v = make_float4(0.f, 0.f, 0.f, 0.f);
            if (gr < M) {
                if (!fused) {
                    v = *reinterpret_cast<const float4*>(A_ext + (size_t)gr * 128 + k0 + c);
                } else {
                    float4 a  = *reinterpret_cast<const float4*>(g_agg + (size_t)gr * 128 + k0 + c);
                    float4 bb = *reinterpret_cast<const float4*>(bias + k0 + c);
                    v.x = fmaxf(fmaf(a.x, srow, bb.x), 0.0f);
                    v.y = fmaxf(fmaf(a.y, srow, bb.y), 0.0f);
                    v.z = fmaxf(fmaf(a.z, srow, bb.z), 0.0f);
                    v.w = fmaxf(fmaf(a.w, srow, bb.w), 0.0f);
                }
            }
            As[lr][c + 0] = __uint_as_float(f2tf32(v.x));
            As[lr][c + 1] = __uint_as_float(f2tf32(v.y));
            As[lr][c + 2] = __uint_as_float(f2tf32(v.z));
            As[lr][c + 3] = __uint_as_float(f2tf32(v.w));
        }
#pragma unroll
        for (int c4 = 0; c4 < 4; c4++) {
            int c = bnb + c4 * 4;
            float4 w = *reinterpret_cast<const float4*>(W + (size_t)(k0 + bk) * 128 + c);
            Bs[bk][c + 0] = __uint_as_float(f2tf32(w.x));
            Bs[bk][c + 1] = __uint_as_float(f2tf32(w.y));
            Bs[bk][c + 2] = __uint_as_float(f2tf32(w.z));
            Bs[bk][c + 3] = __uint_as_float(f2tf32(w.w));
        }
        __syncthreads();

#pragma unroll
        for (int ks = 0; ks < BK; ks += 8) {
            uint32_t afr[4][4], bfr[4][2];
#pragma unroll
            for (int am = 0; am < 4; am++) {
                int m = warp_m * 64 + am * 16;
                afr[am][0] = __float_as_uint(As[m + g8    ][ks + tg    ]);
                afr[am][1] = __float_as_uint(As[m + g8 + 8][ks + tg    ]);
                afr[am][2] = __float_as_uint(As[m + g8    ][ks + tg + 4]);
                afr[am][3] = __float_as_uint(As[m + g8 + 8][ks + tg + 4]);
            }
#pragma unroll
            for (int an = 0; an < 4; an++) {
                int nn = warp_n * 32 + an * 8;
                bfr[an][0] = __float_as_uint(Bs[ks + tg    ][nn + g8]);
                bfr[an][1] = __float_as_uint(Bs[ks + tg + 4][nn + g8]);
            }
#pragma unroll
            for (int am = 0; am < 4; am++)
#pragma unroll
                for (int an = 0; an < 4; an++)
                    mma_tf32(acc[am][an], afr[am], bfr[an]);
        }
        __syncthreads();
    }

    // epilogue: scale by dinv[row], write bf16 payload only
#pragma unroll
    for (int am = 0; am < 4; am++) {
        int r1 = row0 + warp_m * 64 + am * 16 + g8;
        int r2 = r1 + 8;
        float s1 = (r1 < M) ? g_dinv[r1] : 0.0f;
        float s2 = (r2 < M) ? g_dinv[r2] : 0.0f;
#pragma unroll
        for (int an = 0; an < 4; an++) {
            int nn = warp_n * 32 + an * 8 + tg * 2;
            if (r1 < M)
                *reinterpret_cast<__nv_bfloat162*>(g_xwsb + (size_t)r1 * 128 + nn) =
                    __floats2bfloat162_rn(acc[am][an][0] * s1, acc[am][an][1] * s1);
            if (r2 < M)
                *reinterpret_cast<__nv_bfloat162*>(g_xwsb + (size_t)r2 * 128 + nn) =
                    __floats2bfloat162_rn(acc[am][an][2] * s2, acc[am][an][3] * s2);
        }
    }
}

// ---------------- CSR aggregation: agg[d] = xws[d] + sum_{s in N(d)} xws[s] ----
// One warp per dst node; lane owns 4 features (8B bf16), fp32 accumulators,
// single float4 store per lane. NO atomics.
__global__ __launch_bounds__(256) void k_aggregate(int n) {
    int node = (blockIdx.x * blockDim.x + threadIdx.x) >> 5;
    int lane = threadIdx.x & 31;
    if (node >= n) return;

    const size_t fo = (size_t)lane * 4;
    // self-loop message
    uint2 q = *reinterpret_cast<const uint2*>(g_xwsb + (size_t)node * 128 + fo);
    float2 lo = __bfloat1622float2(*reinterpret_cast<__nv_bfloat162*>(&q.x));
    float2 hi = __bfloat1622float2(*reinterpret_cast<__nv_bfloat162*>(&q.y));
    float a0 = lo.x, a1 = lo.y, a2 = hi.x, a3 = hi.y;

    int j   = g_rowptr[node];
    int end = g_rowptr[node + 1];

    for (; j + 2 <= end; j += 2) {
        int s0 = g_csrc[j];
        int s1 = g_csrc[j + 1];
        uint2 qa = *reinterpret_cast<const uint2*>(g_xwsb + (size_t)s0 * 128 + fo);
        uint2 qb = *reinterpret_cast<const uint2*>(g_xwsb + (size_t)s1 * 128 + fo);
        float2 la = __bfloat1622float2(*reinterpret_cast<__nv_bfloat162*>(&qa.x));
        float2 ha = __bfloat1622float2(*reinterpret_cast<__nv_bfloat162*>(&qa.y));
        float2 lb = __bfloat1622float2(*reinterpret_cast<__nv_bfloat162*>(&qb.x));
        float2 hb = __bfloat1622float2(*reinterpret_cast<__nv_bfloat162*>(&qb.y));
        a0 += la.x + lb.x; a1 += la.y + lb.y;
        a2 += ha.x + hb.x; a3 += ha.y + hb.y;
    }
    if (j < end) {
        int s0 = g_csrc[j];
        uint2 qa = *reinterpret_cast<const uint2*>(g_xwsb + (size_t)s0 * 128 + fo);
        float2 la = __bfloat1622float2(*reinterpret_cast<__nv_bfloat162*>(&qa.x));
        float2 ha = __bfloat1622float2(*reinterpret_cast<__nv_bfloat162*>(&qa.y));
        a0 += la.x; a1 += la.y; a2 += ha.x; a3 += ha.y;
    }

    *reinterpret_cast<float4*>(g_agg + (size_t)node * 128 + fo) =
        make_float4(a0, a1, a2, a3);
}

// ---------------- pooling (fused layer-2 activation) ----------------------------
__global__ void k_pool_zero() {
    int i = blockIdx.x * blockDim.x + threadIdx.x;
    if (i < NGRAPH * FDIM) g_sums[i] = 0.0f;
    if (i < NGRAPH)        g_cnts[i] = 0.0f;
}

__global__ __launch_bounds__(256) void k_pool(
    const int* __restrict__ batch, const float* __restrict__ bias, int n)
{
    int node = (blockIdx.x * blockDim.x + threadIdx.x) >> 5;
    int lane = threadIdx.x & 31;
    if (node >= n) return;
    int g = batch[node];
    if ((unsigned)g >= (unsigned)NGRAPH) return;
    float s  = g_dinv[node];
    float4 v = *reinterpret_cast<const float4*>(g_agg + (size_t)node * 128 + lane * 4);
    float4 bb = *reinterpret_cast<const float4*>(bias + lane * 4);
    float4 r;
    r.x = fmaxf(fmaf(v.x, s, bb.x), 0.0f);
    r.y = fmaxf(fmaf(v.y, s, bb.y), 0.0f);
    r.z = fmaxf(fmaf(v.z, s, bb.z), 0.0f);
    r.w = fmaxf(fmaf(v.w, s, bb.w), 0.0f);
    float* p = g_sums + g * 128 + lane * 4;
    asm volatile("red.global.add.v4.f32 [%0], {%1, %2, %3, %4};"
                 :: "l"(p), "f"(r.x), "f"(r.y), "f"(r.z), "f"(r.w) : "memory");
    if (lane == 0) atomicAdd(&g_cnts[g], 1.0f);
}

// ---------------- final head: out[g,o] = (sums[g]/cnt[g]) @ Wlin + blin --------
__global__ void k_final(const float* __restrict__ Wlin, const float* __restrict__ blin,
                        float* __restrict__ out)
{
    int tid = threadIdx.x;
    if (tid >= NGRAPH * 10) return;
    int g = tid / 10;
    int o = tid % 10;
    float inv = 1.0f / fmaxf(g_cnts[g], 1.0f);
    float acc = 0.0f;
#pragma unroll 4
    for (int c = 0; c < 128; c++)
        acc += g_sums[g * 128 + c] * Wlin[c * 10 + o];
    out[tid] = acc * inv + blin[o];
}

// ---------------- launch --------------------------------------------------------
extern "C" void kernel_launch(void* const* d_in, const int* in_sizes, int n_in,
                              void* d_out, int out_size)
{
    const float* x     = (const float*)d_in[0];
    const int*   ei    = (const int*)d_in[1];    // int32 (JAX x64 disabled)
    const int*   batch = (const int*)d_in[2];    // int32
    const float* W1    = (const float*)d_in[3];
    const float* b1    = (const float*)d_in[4];
    const float* W2    = (const float*)d_in[5];
    const float* b2    = (const float*)d_in[6];
    const float* Wlin  = (const float*)d_in[7];
    const float* blin  = (const float*)d_in[8];
    float*       out   = (float*)d_out;

    const int n = in_sizes[0] / FDIM;     // 100000
    const int e = in_sizes[1] / 2;        // 1600000
    const int* src = ei;
    const int* dst = ei + e;

    const int TB = 256;
    int nb_n    = (n + TB - 1) / TB;
    int nb_e    = (e + TB - 1) / TB;
    int nb_gemm = (n + 127) / 128;
    int nb_w    = ((n * 32) + TB - 1) / TB;   // one warp/node
    int nblk    = (n + 1023) / 1024;          // scan blocks (98 <= 256)

    // degrees + dinv
    k_deg_zero <<<nb_n, TB>>>(n);
    k_deg_count<<<nb_e, TB>>>(dst, e, n);
    k_dinv     <<<nb_n, TB>>>(n);

    // CSR build (by dst)
    k_scan1  <<<nblk, TB>>>(n);
    k_scan2  <<<1, TB>>>(nblk);
    k_scan3  <<<nb_n, TB>>>(n, e);
    k_scatter<<<nb_e, TB>>>(src, dst, e, n);

    // layer 1
    k_gemm_tf32<<<nb_gemm, TB>>>(x, W1, nullptr, n);
    k_aggregate<<<nb_w, TB>>>(n);

    // layer 2 (A = relu(agg*dinv + b1) fused in A-load)
    k_gemm_tf32<<<nb_gemm, TB>>>(nullptr, W2, b1, n);
    k_aggregate<<<nb_w, TB>>>(n);

    // pooling (fused relu(agg*dinv + b2)) + head
    k_pool_zero<<<(NGRAPH * FDIM + TB - 1) / TB, TB>>>();
    k_pool     <<<nb_w, TB>>>(batch, b2, n);
    k_final    <<<1, 1024>>>(Wlin, blin, out);
}

// round 11
// speedup vs baseline: 2.7669x; 1.1600x over previous
#include <cuda_runtime.h>
#include <cuda_bf16.h>
#include <cstdint>

#define MAXN 100000
#define MAXE 1600000
#define FDIM 128
#define NGRAPH 64
#define BK 64
#define KS 72   // BK + 8 bf16 padding

// ---------------- scratch (device globals) --------------------------------------
__device__ float          g_dinv[MAXN];
__device__ int            g_deg [MAXN];
__device__ int            g_rowptr[MAXN + 1];
__device__ int            g_cursor[MAXN];
__device__ int            g_csrc[MAXE];
__device__ int            g_blksum[256];
__device__ __nv_bfloat16  g_xwsb[(size_t)MAXN * FDIM];   // (A@W)*dinv[row] payload
__device__ __nv_bfloat16  g_h   [(size_t)MAXN * FDIM];   // activated layer output
__device__ __nv_bfloat16  g_wt  [FDIM * FDIM];           // W^T bf16, [n][k]
__device__ float          g_sums[NGRAPH * FDIM];
__device__ float          g_cnts[NGRAPH];

// ---------------- helpers -------------------------------------------------------
__device__ __forceinline__ void mma_bf16(float* c, const uint32_t* a, const uint32_t* b) {
    asm volatile("mma.sync.aligned.m16n8k16.row.col.f32.bf16.bf16.f32 "
        "{%0,%1,%2,%3}, {%4,%5,%6,%7}, {%8,%9}, {%0,%1,%2,%3};"
        : "+f"(c[0]), "+f"(c[1]), "+f"(c[2]), "+f"(c[3])
        : "r"(a[0]), "r"(a[1]), "r"(a[2]), "r"(a[3]), "r"(b[0]), "r"(b[1]));
}

// ---------------- degree / dinv -------------------------------------------------
__global__ void k_deg_zero(int n) {
    int i = blockIdx.x * blockDim.x + threadIdx.x;
    if (i < n) g_deg[i] = 0;
}
__global__ void k_deg_count(const int* __restrict__ dst, int e, int n) {
    int i = blockIdx.x * blockDim.x + threadIdx.x;
    if (i >= e) return;
    int d = dst[i];
    if ((unsigned)d < (unsigned)n) atomicAdd(&g_deg[d], 1);
}
__global__ void k_dinv(int n) {
    int i = blockIdx.x * blockDim.x + threadIdx.x;
    if (i < n) g_dinv[i] = rsqrtf((float)(g_deg[i] + 1));
}

// ---------------- exclusive scan of g_deg -> g_rowptr ---------------------------
__global__ __launch_bounds__(256) void k_scan1(int n) {
    __shared__ int sh[256];
    int t = threadIdx.x;
    int base = blockIdx.x * 1024 + t * 4;
    int v[4];
#pragma unroll
    for (int i = 0; i < 4; i++) v[i] = (base + i < n) ? g_deg[base + i] : 0;
    int s = v[0] + v[1] + v[2] + v[3];
    sh[t] = s; __syncthreads();
    for (int off = 1; off < 256; off <<= 1) {
        int x = (t >= off) ? sh[t - off] : 0;
        __syncthreads();
        sh[t] += x;
        __syncthreads();
    }
    if (t == 255) g_blksum[blockIdx.x] = sh[255];
    int run = sh[t] - s;
#pragma unroll
    for (int i = 0; i < 4; i++) {
        if (base + i < n) g_rowptr[base + i] = run;
        run += v[i];
    }
}
__global__ __launch_bounds__(256) void k_scan2(int nblk) {
    __shared__ int sh[256];
    int t = threadIdx.x;
    int v = (t < nblk) ? g_blksum[t] : 0;
    sh[t] = v; __syncthreads();
    for (int off = 1; off < 256; off <<= 1) {
        int x = (t >= off) ? sh[t - off] : 0;
        __syncthreads();
        sh[t] += x;
        __syncthreads();
    }
    g_blksum[t] = sh[t] - v;
}
__global__ void k_scan3(int n, int e) {
    int i = blockIdx.x * blockDim.x + threadIdx.x;
    if (i < n) {
        int r = g_rowptr[i] + g_blksum[i >> 10];
        g_rowptr[i] = r;
        g_cursor[i] = r;
    }
    if (i == 0) g_rowptr[n] = e;
}

// ---------------- scatter edges into CSR ----------------------------------------
__global__ void k_scatter(const int* __restrict__ src, const int* __restrict__ dst,
                          int e, int n) {
    int i = blockIdx.x * blockDim.x + threadIdx.x;
    if (i >= e) return;
    int s = src[i], d = dst[i];
    if ((unsigned)s >= (unsigned)n || (unsigned)d >= (unsigned)n) return;
    int pos = atomicAdd(&g_cursor[d], 1);
    if ((unsigned)pos < (unsigned)e) g_csrc[pos] = s;
}

// ---------------- W prep: W[k][n] fp32 -> g_wt[n][k] bf16 -----------------------
__global__ void k_wprep(const float* __restrict__ W) {
    int oid = blockIdx.x * blockDim.x + threadIdx.x;    // 0..8191
    if (oid >= FDIM * FDIM / 2) return;
    int nI = oid & 127;           // coalesced reads across n
    int k  = (oid >> 7) * 2;      // k pair
    float w0 = W[(size_t)k * 128 + nI];
    float w1 = W[(size_t)(k + 1) * 128 + nI];
    *reinterpret_cast<__nv_bfloat162*>(g_wt + (size_t)nI * 128 + k) =
        __floats2bfloat162_rn(w0, w1);
}

// ---------------- bf16 tensor-core GEMM -----------------------------------------
// g_xwsb = bf16( A[M,128] @ W[128,128] * dinv[row] )
// A32 != null : A read as fp32 (layer-1 input x), converted in smem store
// A32 == null : A read as bf16 from g_h (layer-2)
// Block tile 128x128, 256 thr (8 warps 2x4), warp 64x32, 4x4 m16n8k16 atoms.
__global__ __launch_bounds__(256) void k_gemm_bf16(const float* __restrict__ A32, int M)
{
    __shared__ __nv_bfloat16 As[128][KS];   // [m][k]
    __shared__ __nv_bfloat16 Bs[128][KS];   // [n][k]  (W^T layout)

    const int tid    = threadIdx.x;
    const int wid    = tid >> 5;
    const int lane   = tid & 31;
    const int g8     = lane >> 2;
    const int tg     = lane & 3;
    const int warp_m = wid >> 2;
    const int warp_n = wid & 3;
    const int row0   = blockIdx.x * 128;

    float acc[4][4][4];
#pragma unroll
    for (int i = 0; i < 4; i++)
#pragma unroll
        for (int j = 0; j < 4; j++)
#pragma unroll
            for (int r = 0; r < 4; r++) acc[i][j][r] = 0.0f;

    const int lr = tid >> 1;             // A row in tile (0..127)
    const int cb = (tid & 1) * 32;       // col base within chunk
    const int gr = row0 + lr;

    for (int k0 = 0; k0 < 128; k0 += BK) {
        // ---- A chunk ----
        if (A32 != nullptr) {
#pragma unroll
            for (int i = 0; i < 8; i++) {
                float4 v = make_float4(0.f, 0.f, 0.f, 0.f);
                if (gr < M)
                    v = *reinterpret_cast<const float4*>(A32 + (size_t)gr * 128 + k0 + cb + i * 4);
                __nv_bfloat162 p0 = __floats2bfloat162_rn(v.x, v.y);
                __nv_bfloat162 p1 = __floats2bfloat162_rn(v.z, v.w);
                *reinterpret_cast<__nv_bfloat162*>(&As[lr][cb + i * 4 + 0]) = p0;
                *reinterpret_cast<__nv_bfloat162*>(&As[lr][cb + i * 4 + 2]) = p1;
            }
        } else {
#pragma unroll
            for (int i = 0; i < 4; i++) {
                uint4 v = make_uint4(0u, 0u, 0u, 0u);
                if (gr < M)
                    v = *reinterpret_cast<const uint4*>(g_h + (size_t)gr * 128 + k0 + cb + i * 8);
                *reinterpret_cast<uint4*>(&As[lr][cb + i * 8]) = v;
            }
        }
        // ---- B chunk from pre-transposed g_wt ----
        {
            int nB = tid >> 1;
            int kb = (tid & 1) * 32;
#pragma unroll
            for (int i = 0; i < 4; i++) {
                uint4 v = *reinterpret_cast<const uint4*>(g_wt + (size_t)nB * 128 + k0 + kb + i * 8);
                *reinterpret_cast<uint4*>(&Bs[nB][kb + i * 8]) = v;
            }
        }
        __syncthreads();

        // ---- 4 k16-steps of mma ----
#pragma unroll
        for (int ks = 0; ks < BK; ks += 16) {
            uint32_t afr[4][4], bfr[4][2];
#pragma unroll
            for (int am = 0; am < 4; am++) {
                int m = warp_m * 64 + am * 16;
                afr[am][0] = *reinterpret_cast<const uint32_t*>(&As[m + g8    ][ks + 2 * tg    ]);
                afr[am][1] = *reinterpret_cast<const uint32_t*>(&As[m + g8 + 8][ks + 2 * tg    ]);
                afr[am][2] = *reinterpret_cast<const uint32_t*>(&As[m + g8    ][ks + 2 * tg + 8]);
                afr[am][3] = *reinterpret_cast<const uint32_t*>(&As[m + g8 + 8][ks + 2 * tg + 8]);
            }
#pragma unroll
            for (int an = 0; an < 4; an++) {
                int nn = warp_n * 32 + an * 8;
                bfr[an][0] = *reinterpret_cast<const uint32_t*>(&Bs[nn + g8][ks + 2 * tg    ]);
                bfr[an][1] = *reinterpret_cast<const uint32_t*>(&Bs[nn + g8][ks + 2 * tg + 8]);
            }
#pragma unroll
            for (int am = 0; am < 4; am++)
#pragma unroll
                for (int an = 0; an < 4; an++)
                    mma_bf16(acc[am][an], afr[am], bfr[an]);
        }
        __syncthreads();
    }

    // ---- epilogue: scale by dinv[row], write bf16 payload ----
#pragma unroll
    for (int am = 0; am < 4; am++) {
        int r1 = row0 + warp_m * 64 + am * 16 + g8;
        int r2 = r1 + 8;
        float s1 = (r1 < M) ? g_dinv[r1] : 0.0f;
        float s2 = (r2 < M) ? g_dinv[r2] : 0.0f;
#pragma unroll
        for (int an = 0; an < 4; an++) {
            int nn = warp_n * 32 + an * 8 + tg * 2;
            if (r1 < M)
                *reinterpret_cast<__nv_bfloat162*>(g_xwsb + (size_t)r1 * 128 + nn) =
                    __floats2bfloat162_rn(acc[am][an][0] * s1, acc[am][an][1] * s1);
            if (r2 < M)
                *reinterpret_cast<__nv_bfloat162*>(g_xwsb + (size_t)r2 * 128 + nn) =
                    __floats2bfloat162_rn(acc[am][an][2] * s2, acc[am][an][3] * s2);
        }
    }
}

// ---------------- CSR aggregation + fused activation ----------------------------
// sum = xws[d] + sum_{s in N(d)} xws[s];  act = relu(sum * dinv[d] + bias)
// batch == null : write act as bf16 to g_h (feeds next GEMM)
// batch != null : pool directly — REDG act into g_sums[batch[d]] (+count)
__global__ __launch_bounds__(256) void k_aggregate(
    const float* __restrict__ bias, const int* __restrict__ batch, int n)
{
    int node = (blockIdx.x * blockDim.x + threadIdx.x) >> 5;
    int lane = threadIdx.x & 31;
    if (node >= n) return;

    const int fo = lane * 4;
    uint2 q = *reinterpret_cast<const uint2*>(g_xwsb + (size_t)node * 128 + fo);
    float2 lo = __bfloat1622float2(*reinterpret_cast<__nv_bfloat162*>(&q.x));
    float2 hi = __bfloat1622float2(*reinterpret_cast<__nv_bfloat162*>(&q.y));
    float a0 = lo.x, a1 = lo.y, a2 = hi.x, a3 = hi.y;

    int j   = g_rowptr[node];
    int end = g_rowptr[node + 1];

    for (; j + 4 <= end; j += 4) {
        int s0 = g_csrc[j], s1 = g_csrc[j + 1], s2 = g_csrc[j + 2], s3 = g_csrc[j + 3];
        uint2 qa = *reinterpret_cast<const uint2*>(g_xwsb + (size_t)s0 * 128 + fo);
        uint2 qb = *reinterpret_cast<const uint2*>(g_xwsb + (size_t)s1 * 128 + fo);
        uint2 qc = *reinterpret_cast<const uint2*>(g_xwsb + (size_t)s2 * 128 + fo);
        uint2 qd = *reinterpret_cast<const uint2*>(g_xwsb + (size_t)s3 * 128 + fo);
        float2 la = __bfloat1622float2(*reinterpret_cast<__nv_bfloat162*>(&qa.x));
        float2 ha = __bfloat1622float2(*reinterpret_cast<__nv_bfloat162*>(&qa.y));
        float2 lb = __bfloat1622float2(*reinterpret_cast<__nv_bfloat162*>(&qb.x));
        float2 hb = __bfloat1622float2(*reinterpret_cast<__nv_bfloat162*>(&qb.y));
        float2 lc = __bfloat1622float2(*reinterpret_cast<__nv_bfloat162*>(&qc.x));
        float2 hc = __bfloat1622float2(*reinterpret_cast<__nv_bfloat162*>(&qc.y));
        float2 ld = __bfloat1622float2(*reinterpret_cast<__nv_bfloat162*>(&qd.x));
        float2 hd = __bfloat1622float2(*reinterpret_cast<__nv_bfloat162*>(&qd.y));
        a0 += (la.x + lb.x) + (lc.x + ld.x);
        a1 += (la.y + lb.y) + (lc.y + ld.y);
        a2 += (ha.x + hb.x) + (hc.x + hd.x);
        a3 += (ha.y + hb.y) + (hc.y + hd.y);
    }
    for (; j < end; j++) {
        int s0 = g_csrc[j];
        uint2 qa = *reinterpret_cast<const uint2*>(g_xwsb + (size_t)s0 * 128 + fo);
        float2 la = __bfloat1622float2(*reinterpret_cast<__nv_bfloat162*>(&qa.x));
        float2 ha = __bfloat1622float2(*reinterpret_cast<__nv_bfloat162*>(&qa.y));
        a0 += la.x; a1 += la.y; a2 += ha.x; a3 += ha.y;
    }

    float s = g_dinv[node];
    float4 bb = *reinterpret_cast<const float4*>(bias + fo);
    float r0 = fmaxf(fmaf(a0, s, bb.x), 0.0f);
    float r1 = fmaxf(fmaf(a1, s, bb.y), 0.0f);
    float r2 = fmaxf(fmaf(a2, s, bb.z), 0.0f);
    float r3 = fmaxf(fmaf(a3, s, bb.w), 0.0f);

    if (batch == nullptr) {
        uint2 o;
        *reinterpret_cast<__nv_bfloat162*>(&o.x) = __floats2bfloat162_rn(r0, r1);
        *reinterpret_cast<__nv_bfloat162*>(&o.y) = __floats2bfloat162_rn(r2, r3);
        *reinterpret_cast<uint2*>(g_h + (size_t)node * 128 + fo) = o;
    } else {
        int g = batch[node];
        if ((unsigned)g < (unsigned)NGRAPH) {
            float* p = g_sums + g * 128 + fo;
            asm volatile("red.global.add.v4.f32 [%0], {%1, %2, %3, %4};"
                         :: "l"(p), "f"(r0), "f"(r1), "f"(r2), "f"(r3) : "memory");
            if (lane == 0) atomicAdd(&g_cnts[g], 1.0f);
        }
    }
}

// ---------------- zero pools ----------------------------------------------------
__global__ void k_pool_zero() {
    int i = blockIdx.x * blockDim.x + threadIdx.x;
    if (i < NGRAPH * FDIM) g_sums[i] = 0.0f;
    if (i < NGRAPH)        g_cnts[i] = 0.0f;
}

// ---------------- final head ----------------------------------------------------
__global__ void k_final(const float* __restrict__ Wlin, const float* __restrict__ blin,
                        float* __restrict__ out)
{
    int tid = threadIdx.x;
    if (tid >= NGRAPH * 10) return;
    int g = tid / 10;
    int o = tid % 10;
    float inv = 1.0f / fmaxf(g_cnts[g], 1.0f);
    float acc = 0.0f;
#pragma unroll 4
    for (int c = 0; c < 128; c++)
        acc += g_sums[g * 128 + c] * Wlin[c * 10 + o];
    out[tid] = acc * inv + blin[o];
}

// ---------------- launch --------------------------------------------------------
extern "C" void kernel_launch(void* const* d_in, const int* in_sizes, int n_in,
                              void* d_out, int out_size)
{
    const float* x     = (const float*)d_in[0];
    const int*   ei    = (const int*)d_in[1];    // int32 (JAX x64 disabled)
    const int*   batch = (const int*)d_in[2];    // int32
    const float* W1    = (const float*)d_in[3];
    const float* b1    = (const float*)d_in[4];
    const float* W2    = (const float*)d_in[5];
    const float* b2    = (const float*)d_in[6];
    const float* Wlin  = (const float*)d_in[7];
    const float* blin  = (const float*)d_in[8];
    float*       out   = (float*)d_out;

    const int n = in_sizes[0] / FDIM;     // 100000
    const int e = in_sizes[1] / 2;        // 1600000
    const int* src = ei;
    const int* dst = ei + e;

    const int TB = 256;
    int nb_n    = (n + TB - 1) / TB;
    int nb_e    = (e + TB - 1) / TB;
    int nb_gemm = (n + 127) / 128;
    int nb_w    = ((n * 32) + TB - 1) / TB;   // one warp/node
    int nblk    = (n + 1023) / 1024;

    // zero pools + degrees + dinv
    k_pool_zero<<<(NGRAPH * FDIM + TB - 1) / TB, TB>>>();
    k_deg_zero <<<nb_n, TB>>>(n);
    k_deg_count<<<nb_e, TB>>>(dst, e, n);
    k_dinv     <<<nb_n, TB>>>(n);

    // CSR build (by dst)
    k_scan1  <<<nblk, TB>>>(n);
    k_scan2  <<<1, TB>>>(nblk);
    k_scan3  <<<nb_n, TB>>>(n, e);
    k_scatter<<<nb_e, TB>>>(src, dst, e, n);

    // layer 1
    k_wprep    <<<32, TB>>>(W1);
    k_gemm_bf16<<<nb_gemm, TB>>>(x, n);
    k_aggregate<<<nb_w, TB>>>(b1, nullptr, n);   // -> g_h

    // layer 2
    k_wprep    <<<32, TB>>>(W2);
    k_gemm_bf16<<<nb_gemm, TB>>>(nullptr, n);    // reads g_h
    k_aggregate<<<nb_w, TB>>>(b2, batch, n);     // -> pooled sums directly

    // head
    k_final<<<1, 1024>>>(Wlin, blin, out);
}